// round 1
// baseline (speedup 1.0000x reference)
#include <cuda_runtime.h>
#include <math.h>

// Problem constants (shapes are fixed per the reference; sizes re-derived from in_sizes)
#define NB 16
#define MAX_NODES 100000

// Scratch (no allocation allowed -> __device__ globals)
__device__ float g_W[128 * 64];    // rows 0..63: W_msg[k][o], rows 64..127: W_self[k][o]
__device__ float g_bias[128];      // [0:64) b_msg, [64:128) b_self
__device__ int   g_deg[MAX_NODES];

// ---------------------------------------------------------------------------
// Kernel 1: collapse bases -> W (128x64, k-major) and biases
// basis_*_wt: [in=64, out=64, B=16], basis_*_bias: [out=64, B=16], lin_comb: [1,16]
// ---------------------------------------------------------------------------
__global__ void combine_kernel(const float* __restrict__ wt_msg,
                               const float* __restrict__ b_msg,
                               const float* __restrict__ wt_self,
                               const float* __restrict__ b_self,
                               const float* __restrict__ lin_comb) {
    __shared__ float c[NB];
    if (threadIdx.x < NB) c[threadIdx.x] = lin_comb[threadIdx.x];
    __syncthreads();

    for (int idx = threadIdx.x; idx < 64 * 64; idx += blockDim.x) {
        const float* pm = wt_msg + idx * NB;
        const float* ps = wt_self + idx * NB;
        float am = 0.f, as = 0.f;
#pragma unroll
        for (int b = 0; b < NB; b++) {
            am += pm[b] * c[b];
            as += ps[b] * c[b];
        }
        int i = idx >> 6, o = idx & 63;     // idx = i*64 + o
        g_W[i * 64 + o] = am;               // W_msg
        g_W[(64 + i) * 64 + o] = as;        // W_self
    }
    for (int o = threadIdx.x; o < 64; o += blockDim.x) {
        float am = 0.f, as = 0.f;
#pragma unroll
        for (int b = 0; b < NB; b++) {
            am += b_msg[o * NB + b] * c[b];
            as += b_self[o * NB + b] * c[b];
        }
        g_bias[o] = am;
        g_bias[64 + o] = as;
    }
}

// ---------------------------------------------------------------------------
// Kernel 2: zero the accumulator (d_out doubles as S) and degree counts
// ---------------------------------------------------------------------------
__global__ void zero_kernel(float4* __restrict__ out4, int n_nodes) {
    const int stride = gridDim.x * blockDim.x;
    const int total4 = n_nodes * 16;  // n_nodes*64 floats / 4
    for (int i = blockIdx.x * blockDim.x + threadIdx.x; i < total4; i += stride)
        out4[i] = make_float4(0.f, 0.f, 0.f, 0.f);
    for (int i = blockIdx.x * blockDim.x + threadIdx.x; i < n_nodes; i += stride)
        g_deg[i] = 0;
}

// ---------------------------------------------------------------------------
// Kernel 3: edge scatter. 16 threads per edge, one float4 each.
// S[dst] += x[src]  via red.global.add.v4.f32 ; deg[dst] += 1 (lane q==0)
// x (25.6MB) and S (25.6MB) both fit in L2.
// ---------------------------------------------------------------------------
__global__ void scatter_kernel(const float4* __restrict__ x4,
                               const int* __restrict__ ei,
                               float* __restrict__ S,
                               int n_edges) {
    int gid = blockIdx.x * blockDim.x + threadIdx.x;
    int e = gid >> 4;
    int q = gid & 15;
    if (e >= n_edges) return;
    int src = ei[e];
    int dst = ei[n_edges + e];
    float4 v = x4[src * 16 + q];
    float* p = S + dst * 64 + q * 4;
    asm volatile("red.global.add.v4.f32 [%0], {%1,%2,%3,%4};"
                 :: "l"(p), "f"(v.x), "f"(v.y), "f"(v.z), "f"(v.w)
                 : "memory");
    if (q == 0) atomicAdd(&g_deg[dst], 1);
}

// ---------------------------------------------------------------------------
// Kernel 4: fused  out = L2norm( S @ W_msg + deg*b_msg + x @ W_self + b_self )
// Treated as [S|x] (64-node tile x K=128) @ W (128x64) in shared memory.
// 256 threads/block, 64 nodes/block, each thread: 1 node x 16 columns.
// In-place on d_out: tile of S is staged to shared before any store.
// ---------------------------------------------------------------------------
#define A_STRIDE 132  // 128 + 4 pad: node row step -> bank step 4 (conflict-free reads)

__global__ void out_kernel(const float* __restrict__ x,
                           float* __restrict__ S,   // aliases d_out
                           int n_nodes) {
    extern __shared__ float sh[];
    float* shA = sh;                 // [64][A_STRIDE]
    float* shW = sh + 64 * A_STRIDE; // [128][64]
    const int tid = threadIdx.x;
    const int node0 = blockIdx.x * 64;

    // Stage W (8192 floats, float4 coalesced)
    for (int i = tid; i < 2048; i += 256)
        ((float4*)shW)[i] = ((const float4*)g_W)[i];

    // Stage A = [S | x] for 64 nodes (zero-pad past n_nodes)
    for (int idx = tid; idx < 4096; idx += 256) {
        int nd = idx >> 6, j = idx & 63;
        int gn = node0 + nd;
        float sv = 0.f, xv = 0.f;
        if (gn < n_nodes) {
            sv = S[gn * 64 + j];
            xv = x[gn * 64 + j];
        }
        shA[nd * A_STRIDE + j] = sv;
        shA[nd * A_STRIDE + 64 + j] = xv;
    }
    __syncthreads();

    const int tx = tid & 3;        // column group: cols [16*tx, 16*tx+16)
    const int nd = tid >> 2;       // node within tile (0..63)
    const int col0 = tx * 16;
    const int gn = node0 + nd;

    float acc[16];
#pragma unroll
    for (int c = 0; c < 16; c++) acc[c] = 0.f;

    const float* aRow = shA + nd * A_STRIDE;
#pragma unroll 4
    for (int k = 0; k < 128; k++) {
        float a = aRow[k];
        const float4* w4 = (const float4*)(shW + k * 64 + col0);
#pragma unroll
        for (int w = 0; w < 4; w++) {
            float4 wv = w4[w];
            acc[4 * w + 0] += a * wv.x;
            acc[4 * w + 1] += a * wv.y;
            acc[4 * w + 2] += a * wv.z;
            acc[4 * w + 3] += a * wv.w;
        }
    }

    // Bias + L2 normalize (reduce across the 4 consecutive lanes of this node)
    float degf = (gn < n_nodes) ? (float)g_deg[gn] : 0.f;
    float ss = 0.f;
#pragma unroll
    for (int c = 0; c < 16; c++) {
        int col = col0 + c;
        acc[c] += degf * g_bias[col] + g_bias[64 + col];
        ss += acc[c] * acc[c];
    }
    ss += __shfl_xor_sync(0xffffffffu, ss, 1);
    ss += __shfl_xor_sync(0xffffffffu, ss, 2);
    float inv = 1.f / fmaxf(sqrtf(ss), 1e-12f);

    if (gn < n_nodes) {
        float4* o4 = (float4*)(S + gn * 64 + col0);
#pragma unroll
        for (int w = 0; w < 4; w++)
            o4[w] = make_float4(acc[4 * w + 0] * inv, acc[4 * w + 1] * inv,
                                acc[4 * w + 2] * inv, acc[4 * w + 3] * inv);
    }
}

// ---------------------------------------------------------------------------
// Launch. Inputs (metadata order):
//  0: x [N,64] f32 | 1: edge_index [2,E] i32 | 2: basis_msg_wt [64,64,16]
//  3: basis_msg_bias [64,16] | 4: basis_self_wt | 5: basis_self_bias
//  6: lin_comb [1,16]        out: [N,64] f32
// ---------------------------------------------------------------------------
extern "C" void kernel_launch(void* const* d_in, const int* in_sizes, int n_in,
                              void* d_out, int out_size) {
    const float* x  = (const float*)d_in[0];
    const int*   ei = (const int*)d_in[1];
    const float* wm = (const float*)d_in[2];
    const float* bm = (const float*)d_in[3];
    const float* ws = (const float*)d_in[4];
    const float* bs = (const float*)d_in[5];
    const float* lc = (const float*)d_in[6];
    float* out = (float*)d_out;

    const int n_nodes = in_sizes[0] / 64;
    const int n_edges = in_sizes[1] / 2;

    combine_kernel<<<1, 256>>>(wm, bm, ws, bs, lc);
    zero_kernel<<<1024, 256>>>((float4*)out, n_nodes);

    int sc_threads = n_edges * 16;
    scatter_kernel<<<(sc_threads + 255) / 256, 256>>>((const float4*)x, ei, out, n_edges);

    const int smem = (64 * A_STRIDE + 128 * 64) * (int)sizeof(float);  // 66560 B
    cudaFuncSetAttribute(out_kernel, cudaFuncAttributeMaxDynamicSharedMemorySize, smem);
    out_kernel<<<(n_nodes + 63) / 64, 256, smem>>>(x, out, n_nodes);
}

// round 5
// speedup vs baseline: 1.9438x; 1.9438x over previous
#include <cuda_runtime.h>
#include <math.h>

#define NB 16
#define MAX_NODES 100000

typedef unsigned long long u64;

// Scratch (no allocation allowed -> __device__ globals)
__device__ float g_W[128 * 64];    // rows 0..63: W_msg[k][o], rows 64..127: W_self[k][o]
__device__ float g_bias[128];      // [0:64) b_msg, [64:128) b_self
__device__ int   g_deg[MAX_NODES];

// ---------------- packed f32x2 helpers (Blackwell FFMA2 via PTX) ----------------
__device__ __forceinline__ u64 pack2_dup(float v) {
    u64 r; asm("mov.b64 %0, {%1,%1};" : "=l"(r) : "f"(v)); return r;
}
__device__ __forceinline__ void unpack2(u64 v, float& lo, float& hi) {
    asm("mov.b64 {%0,%1}, %2;" : "=f"(lo), "=f"(hi) : "l"(v));
}
__device__ __forceinline__ u64 ffma2(u64 a, u64 b, u64 c) {
    u64 d; asm("fma.rn.f32x2 %0, %1, %2, %3;" : "=l"(d) : "l"(a), "l"(b), "l"(c)); return d;
}

// ---------------------------------------------------------------------------
// Kernel 1: collapse bases -> W (128x64, k-major) and biases
// ---------------------------------------------------------------------------
__global__ void combine_kernel(const float* __restrict__ wt_msg,
                               const float* __restrict__ b_msg,
                               const float* __restrict__ wt_self,
                               const float* __restrict__ b_self,
                               const float* __restrict__ lin_comb) {
    __shared__ float c[NB];
    if (threadIdx.x < NB) c[threadIdx.x] = lin_comb[threadIdx.x];
    __syncthreads();

    for (int idx = threadIdx.x; idx < 64 * 64; idx += blockDim.x) {
        const float* pm = wt_msg + idx * NB;
        const float* ps = wt_self + idx * NB;
        float am = 0.f, as = 0.f;
#pragma unroll
        for (int b = 0; b < NB; b++) {
            am += pm[b] * c[b];
            as += ps[b] * c[b];
        }
        int i = idx >> 6, o = idx & 63;
        g_W[i * 64 + o] = am;
        g_W[(64 + i) * 64 + o] = as;
    }
    for (int o = threadIdx.x; o < 64; o += blockDim.x) {
        float am = 0.f, as = 0.f;
#pragma unroll
        for (int b = 0; b < NB; b++) {
            am += b_msg[o * NB + b] * c[b];
            as += b_self[o * NB + b] * c[b];
        }
        g_bias[o] = am;
        g_bias[64 + o] = as;
    }
}

// ---------------------------------------------------------------------------
// Kernel 2: zero the accumulator (d_out doubles as S) and degree counts
// ---------------------------------------------------------------------------
__global__ void zero_kernel(float4* __restrict__ out4, int n_nodes) {
    const int stride = gridDim.x * blockDim.x;
    const int total4 = n_nodes * 16;
    for (int i = blockIdx.x * blockDim.x + threadIdx.x; i < total4; i += stride)
        out4[i] = make_float4(0.f, 0.f, 0.f, 0.f);
    for (int i = blockIdx.x * blockDim.x + threadIdx.x; i < n_nodes; i += stride)
        g_deg[i] = 0;
}

// ---------------------------------------------------------------------------
// Kernel 3: edge scatter. 16 threads per edge, one float4 each (red.v4).
// ---------------------------------------------------------------------------
__global__ void scatter_kernel(const float4* __restrict__ x4,
                               const int* __restrict__ ei,
                               float* __restrict__ S,
                               int n_edges) {
    int gid = blockIdx.x * blockDim.x + threadIdx.x;
    int e = gid >> 4;
    int q = gid & 15;
    if (e >= n_edges) return;
    int src = ei[e];
    int dst = ei[n_edges + e];
    float4 v = x4[src * 16 + q];
    float* p = S + dst * 64 + q * 4;
    asm volatile("red.global.add.v4.f32 [%0], {%1,%2,%3,%4};"
                 :: "l"(p), "f"(v.x), "f"(v.y), "f"(v.z), "f"(v.w)
                 : "memory");
    if (q == 0) atomicAdd(&g_deg[dst], 1);
}

// ---------------------------------------------------------------------------
// Kernel 4: fused  out = L2norm( [S|x] @ [W_msg;W_self] + deg*b_msg + b_self )
// 256 threads, tile = 128 nodes x 64 cols, K = 128.
// A transposed in shared: shA[k][node], stride SA=130 (even: 8B align for
// LDS.64; 2*SA mod 32 = 4 keeps warp a-loads within 2 wavefronts).
// Thread (lane=tid&31, w=tid>>5) -> nodes {2L,2L+1,2L+64,2L+65}, cols w*8..+7.
// Node pairs are memory-adjacent -> a operands are native packed f32x2.
// W access is warp-uniform (broadcast). 16 FFMA2 per thread per k.
// ---------------------------------------------------------------------------
#define SA 130

__global__ __launch_bounds__(256, 2)
void out_kernel(const float* __restrict__ x,
                float* __restrict__ S,   // aliases d_out
                int n_nodes) {
    extern __shared__ float sh[];
    float* shA   = sh;                       // [128][SA]
    float* shW   = sh + 128 * SA;            // [128][64]
    float* s_ss  = shW + 128 * 64;           // [128]
    float* s_inv = s_ss + 128;               // [128]

    const int tid = threadIdx.x;
    const int node0 = blockIdx.x * 128;

    if (tid < 128) s_ss[tid] = 0.f;

    // Stage W (8192 floats, coalesced, conflict-free float4 stores)
    for (int i = tid; i < 2048; i += 256)
        ((float4*)shW)[i] = ((const float4*)g_W)[i];

    // Stage A transposed: rows k 0..63 = S, 64..127 = x
    for (int idx = tid; idx < 2048; idx += 256) {
        int node = idx >> 4, j4 = idx & 15;
        int gn = node0 + node;
        float4 sv = make_float4(0.f, 0.f, 0.f, 0.f);
        float4 xv = sv;
        if (gn < n_nodes) {
            sv = ((const float4*)S)[gn * 16 + j4];
            xv = ((const float4*)x)[gn * 16 + j4];
        }
        int k0 = j4 * 4;
        shA[(k0 + 0) * SA + node] = sv.x;
        shA[(k0 + 1) * SA + node] = sv.y;
        shA[(k0 + 2) * SA + node] = sv.z;
        shA[(k0 + 3) * SA + node] = sv.w;
        shA[(64 + k0 + 0) * SA + node] = xv.x;
        shA[(64 + k0 + 1) * SA + node] = xv.y;
        shA[(64 + k0 + 2) * SA + node] = xv.z;
        shA[(64 + k0 + 3) * SA + node] = xv.w;
    }
    __syncthreads();

    const int lane = tid & 31;
    const int wrp  = tid >> 5;     // 0..7
    const int col0 = wrp * 8;

    u64 acc[2][8];
#pragma unroll
    for (int q = 0; q < 2; q++)
#pragma unroll
        for (int c = 0; c < 8; c++) acc[q][c] = 0ull;

#pragma unroll 8
    for (int k = 0; k < 128; k++) {
        const float* arow = shA + k * SA + 2 * lane;
        u64 a0 = *(const u64*)(arow);          // nodes 2L, 2L+1
        u64 a1 = *(const u64*)(arow + 64);     // nodes 2L+64, 2L+65
        const float4* wrow = (const float4*)(shW + k * 64 + col0);
        float4 w0 = wrow[0];
        float4 w1 = wrow[1];
        u64 wd0 = pack2_dup(w0.x), wd1 = pack2_dup(w0.y);
        u64 wd2 = pack2_dup(w0.z), wd3 = pack2_dup(w0.w);
        u64 wd4 = pack2_dup(w1.x), wd5 = pack2_dup(w1.y);
        u64 wd6 = pack2_dup(w1.z), wd7 = pack2_dup(w1.w);
        acc[0][0] = ffma2(a0, wd0, acc[0][0]);
        acc[0][1] = ffma2(a0, wd1, acc[0][1]);
        acc[0][2] = ffma2(a0, wd2, acc[0][2]);
        acc[0][3] = ffma2(a0, wd3, acc[0][3]);
        acc[0][4] = ffma2(a0, wd4, acc[0][4]);
        acc[0][5] = ffma2(a0, wd5, acc[0][5]);
        acc[0][6] = ffma2(a0, wd6, acc[0][6]);
        acc[0][7] = ffma2(a0, wd7, acc[0][7]);
        acc[1][0] = ffma2(a1, wd0, acc[1][0]);
        acc[1][1] = ffma2(a1, wd1, acc[1][1]);
        acc[1][2] = ffma2(a1, wd2, acc[1][2]);
        acc[1][3] = ffma2(a1, wd3, acc[1][3]);
        acc[1][4] = ffma2(a1, wd4, acc[1][4]);
        acc[1][5] = ffma2(a1, wd5, acc[1][5]);
        acc[1][6] = ffma2(a1, wd6, acc[1][6]);
        acc[1][7] = ffma2(a1, wd7, acc[1][7]);
    }

    // Unpack: accf[r][c], r=0..3 -> nodes {2L, 2L+1, 2L+64, 2L+65}
    float accf[4][8];
#pragma unroll
    for (int q = 0; q < 2; q++)
#pragma unroll
        for (int c = 0; c < 8; c++)
            unpack2(acc[q][c], accf[2 * q][c], accf[2 * q + 1][c]);

    int nloc[4];
    nloc[0] = 2 * lane; nloc[1] = 2 * lane + 1;
    nloc[2] = 2 * lane + 64; nloc[3] = 2 * lane + 65;

    float bm[8], bsf[8];
#pragma unroll
    for (int c = 0; c < 8; c++) {
        bm[c]  = g_bias[col0 + c];
        bsf[c] = g_bias[64 + col0 + c];
    }

#pragma unroll
    for (int r = 0; r < 4; r++) {
        int gn = node0 + nloc[r];
        float degf = (gn < n_nodes) ? (float)g_deg[gn] : 0.f;
        float ss = 0.f;
#pragma unroll
        for (int c = 0; c < 8; c++) {
            accf[r][c] += degf * bm[c] + bsf[c];
            ss += accf[r][c] * accf[r][c];
        }
        atomicAdd(&s_ss[nloc[r]], ss);
    }
    __syncthreads();

    if (tid < 128) s_inv[tid] = 1.f / fmaxf(sqrtf(s_ss[tid]), 1e-12f);
    __syncthreads();

#pragma unroll
    for (int r = 0; r < 4; r++) {
        int gn = node0 + nloc[r];
        if (gn < n_nodes) {
            float inv = s_inv[nloc[r]];
            float4 o0 = make_float4(accf[r][0] * inv, accf[r][1] * inv,
                                    accf[r][2] * inv, accf[r][3] * inv);
            float4 o1 = make_float4(accf[r][4] * inv, accf[r][5] * inv,
                                    accf[r][6] * inv, accf[r][7] * inv);
            float4* o = (float4*)(S + gn * 64 + col0);
            o[0] = o0;
            o[1] = o1;
        }
    }
}

// ---------------------------------------------------------------------------
// Launch. Inputs (metadata order):
//  0: x [N,64] f32 | 1: edge_index [2,E] i32 | 2: basis_msg_wt [64,64,16]
//  3: basis_msg_bias [64,16] | 4: basis_self_wt | 5: basis_self_bias
//  6: lin_comb [1,16]        out: [N,64] f32
// ---------------------------------------------------------------------------
extern "C" void kernel_launch(void* const* d_in, const int* in_sizes, int n_in,
                              void* d_out, int out_size) {
    const float* x  = (const float*)d_in[0];
    const int*   ei = (const int*)d_in[1];
    const float* wm = (const float*)d_in[2];
    const float* bm = (const float*)d_in[3];
    const float* ws = (const float*)d_in[4];
    const float* bs = (const float*)d_in[5];
    const float* lc = (const float*)d_in[6];
    float* out = (float*)d_out;

    const int n_nodes = in_sizes[0] / 64;
    const int n_edges = in_sizes[1] / 2;

    combine_kernel<<<1, 256>>>(wm, bm, ws, bs, lc);
    zero_kernel<<<1024, 256>>>((float4*)out, n_nodes);

    int sc_threads = n_edges * 16;
    scatter_kernel<<<(sc_threads + 255) / 256, 256>>>((const float4*)x, ei, out, n_edges);

    const int smem = (128 * SA + 128 * 64 + 256) * (int)sizeof(float);  // 100352 B
    cudaFuncSetAttribute(out_kernel, cudaFuncAttributeMaxDynamicSharedMemorySize, smem);
    out_kernel<<<(n_nodes + 127) / 128, 256, smem>>>(x, out, n_nodes);
}